// round 15
// baseline (speedup 1.0000x reference)
#include <cuda_runtime.h>
#include <cuda_bf16.h>
#include <cstdint>

#define BB 4
#define NN 4096
#define CC 256
#define II 128
#define ROWS (BB*NN)          // 16384
#define SEG 32
#define NSEG (NN/SEG)         // 128
#define BN_EPS 1e-3f

#define GEMM_THREADS 512
#define GEMM_SMEM (2*128*40*2 + 2*256*40*2)   // 61440 bytes

// ---------------- scratch (static device allocations) ----------------
__device__ float d_vt[CC], d_vp[CC];
__device__ float d_ct, d_cp;
__device__ float d_scale[CC], d_shift[CC];
__device__ __nv_bfloat16 d_Wt[CC*CC];       // Wt[n][k] = (wg@ww)[k][n], bf16
__device__ float d_chb[CC];                 // bg @ ww
__device__ __nv_bfloat16 d_hb[(size_t)ROWS*CC];   // h = x@W + chb, bf16 (8 MB)
__device__ float d_st[ROWS], d_sp[ROWS];
__device__ unsigned d_skey[ROWS];           // truncated sortable key | (4095-j)
__device__ unsigned d_ksort[ROWS];          // keys in descending order
__device__ __nv_bfloat162 d_Q[(size_t)ROWS*CC];   // (prefix h, prefix t*h) bf16 (8 MB)
__device__ float2 d_seg[BB*NSEG*CC];        // segment totals
__device__ float2 d_off[BB*NSEG*CC];        // exclusive segment offsets
__device__ int    g_cnt;                    // grid barrier arrive counter
__device__ int    g_gen;                    // grid barrier generation

// ---------------- helpers ----------------------------------------------------
__device__ __forceinline__ unsigned f2sortable(float f) {
    unsigned u = __float_as_uint(f);
    return (u & 0x80000000u) ? ~u : (u | 0x80000000u);
}
__device__ __forceinline__ void ldsm4(uint32_t* r, uint32_t addr) {
    asm volatile("ldmatrix.sync.aligned.m8n8.x4.shared.b16 {%0,%1,%2,%3},[%4];\n"
        : "=r"(r[0]), "=r"(r[1]), "=r"(r[2]), "=r"(r[3]) : "r"(addr));
}
__device__ __forceinline__ void mma_bf16(float* c, const uint32_t* a, uint32_t b0, uint32_t b1) {
    asm volatile("mma.sync.aligned.m16n8k16.row.col.f32.bf16.bf16.f32 "
        "{%0,%1,%2,%3},{%4,%5,%6,%7},{%8,%9},{%0,%1,%2,%3};\n"
        : "+f"(c[0]), "+f"(c[1]), "+f"(c[2]), "+f"(c[3])
        : "r"(a[0]), "r"(a[1]), "r"(a[2]), "r"(a[3]), "r"(b0), "r"(b1));
}
__device__ __forceinline__ void cp_async16(uint32_t saddr, const void* gaddr) {
    asm volatile("cp.async.cg.shared.global [%0], [%1], 16;\n" :: "r"(saddr), "l"(gaddr));
}
__device__ __forceinline__ void cp_commit() {
    asm volatile("cp.async.commit_group;\n");
}
__device__ __forceinline__ void cp_wait0() {
    asm volatile("cp.async.wait_group 0;\n");
}

// software grid barrier: all nBlocks must be co-resident (guaranteed by
// occupancy-sized launch). generation counter makes it reusable w/o reset.
__device__ __forceinline__ void grid_barrier(int nBlocks) {
    __syncthreads();
    if (threadIdx.x == 0) {
        __threadfence();
        int gen = atomicAdd(&g_gen, 0);
        if (atomicAdd(&g_cnt, 1) == nBlocks - 1) {
            g_cnt = 0;
            __threadfence();
            atomicAdd(&g_gen, 1);
        } else {
            while (atomicAdd(&g_gen, 0) == gen) { __nanosleep(64); }
        }
        __threadfence();
    }
    __syncthreads();
}

// ---------------- K0: W = wg@ww (bf16, transposed) + all weight folds ---------
__global__ __launch_bounds__(128) void k_prep(const float* __restrict__ wg,
                                              const float* __restrict__ ww,
                                              const float* __restrict__ bg,
                                              const float* __restrict__ wt,
                                              const float* __restrict__ wp,
                                              const float* __restrict__ wc,
                                              const float* __restrict__ bt,
                                              const float* __restrict__ bp,
                                              const float* __restrict__ gamma,
                                              const float* __restrict__ beta,
                                              const float* __restrict__ bn_mean,
                                              const float* __restrict__ bn_var,
                                              const float* __restrict__ bw) {
    __shared__ float col[II];
    const int n = blockIdx.x;          // 0..255
    const int t = threadIdx.x;         // 0..127
    col[t] = ww[t * CC + n];
    __syncthreads();
    #pragma unroll
    for (int half = 0; half < 2; half++) {
        int c = half * 128 + t;
        float s = 0.f;
        #pragma unroll 4
        for (int j = 0; j < II; j++) s = fmaf(wg[c * II + j], col[j], s);
        d_Wt[n * CC + c] = __float2bfloat16(s);
    }
    if (t == 0) {
        float s = 0.f;
        for (int j = 0; j < II; j++) s = fmaf(bg[j], col[j], s);
        d_chb[n] = s;
    }
    if (t == 1) {
        float s = 0.f;
        for (int k = 0; k < II; k++) s = fmaf(wt[n * II + k], wc[k], s);
        d_vt[n] = s;
    }
    if (t == 2) {
        float s = 0.f;
        for (int k = 0; k < II; k++) s = fmaf(wp[n * II + k], wc[II + k], s);
        d_vp[n] = s;
    }
    if (t == 3) {
        float a = gamma[n] * rsqrtf(bn_var[n] + BN_EPS);
        d_scale[n] = a;
        d_shift[n] = (bw[n] - bn_mean[n]) * a + beta[n];
    }
    if (n == 0 && t == 4) {
        float s = 0.f;
        for (int k = 0; k < II; k++) s = fmaf(bt[k], wc[k], s);
        d_ct = s;
    }
    if (n == 0 && t == 5) {
        float s = 0.f;
        for (int k = 0; k < II; k++) s = fmaf(bp[k], wc[II + k], s);
        d_cp = s;
    }
}

// ---------------- K2: h = x@W + chb, BM=128 x BN=256, one wave ---------------
// 512 threads, 16 warps (4m x 4n), double-buffered; B tiles via cp.async.
__global__ __launch_bounds__(GEMM_THREADS, 1) void k_gemm(const float* __restrict__ x) {
    extern __shared__ __nv_bfloat16 smemb[];
    __nv_bfloat16* As = smemb;                    // [2][128][40]
    __nv_bfloat16* Bs = smemb + 2 * 128 * 40;     // [2][256][40]
    const int tid  = threadIdx.x;
    const int warp = tid >> 5, lane = tid & 31;
    const int wm = warp & 3, wn = warp >> 2;
    const int r0 = blockIdx.x * 128;

    float acc[2][8][4];
    #pragma unroll
    for (int ms = 0; ms < 2; ms++)
        #pragma unroll
        for (int ns = 0; ns < 8; ns++)
            #pragma unroll
            for (int q = 0; q < 4; q++) acc[ms][ns][q] = 0.f;

    float sat[2] = {0.f, 0.f}, sap[2] = {0.f, 0.f};
    const int myc = (tid & 7) * 4;

    const int lrow = lane & 15;
    const int lkof = (lane >> 4) << 3;

    const int bn0 = (tid) >> 2,                bk0 = (tid & 3) * 8;
    const int bn1 = (GEMM_THREADS + tid) >> 2, bk1 = ((GEMM_THREADS + tid) & 3) * 8;

    // ---- prologue: tile 0 ----
    cp_async16((uint32_t)__cvta_generic_to_shared(&Bs[(size_t)bn0 * 40 + bk0]),
               &d_Wt[bn0 * CC + bk0]);
    cp_async16((uint32_t)__cvta_generic_to_shared(&Bs[(size_t)bn1 * 40 + bk1]),
               &d_Wt[bn1 * CC + bk1]);
    cp_commit();
    #pragma unroll
    for (int p = 0; p < 2; p++) {
        int idx = p * GEMM_THREADS + tid;
        int m = idx >> 3, c = (idx & 7) * 4;
        float4 v = *(const float4*)&x[(size_t)(r0 + m) * CC + c];
        sat[p] += v.x*d_vt[myc] + v.y*d_vt[myc+1] + v.z*d_vt[myc+2] + v.w*d_vt[myc+3];
        sap[p] += v.x*d_vp[myc] + v.y*d_vp[myc+1] + v.z*d_vp[myc+2] + v.w*d_vp[myc+3];
        __nv_bfloat162 lo = __floats2bfloat162_rn(v.x, v.y);
        __nv_bfloat162 hi = __floats2bfloat162_rn(v.z, v.w);
        uint2 pk; pk.x = *(uint32_t*)&lo; pk.y = *(uint32_t*)&hi;
        *(uint2*)&As[(size_t)m * 40 + c] = pk;
    }
    cp_wait0();
    __syncthreads();

    #pragma unroll
    for (int t = 0; t < 8; t++) {
        const int pb = t & 1;
        float4 ra[2];
        if (t < 7) {
            const int kk = (t + 1) * 32;
            const int pn = pb ^ 1;
            cp_async16((uint32_t)__cvta_generic_to_shared(
                           &Bs[(size_t)(pn * 256 + bn0) * 40 + bk0]),
                       &d_Wt[bn0 * CC + kk + bk0]);
            cp_async16((uint32_t)__cvta_generic_to_shared(
                           &Bs[(size_t)(pn * 256 + bn1) * 40 + bk1]),
                       &d_Wt[bn1 * CC + kk + bk1]);
            cp_commit();
            #pragma unroll
            for (int p = 0; p < 2; p++) {
                int idx = p * GEMM_THREADS + tid;
                int m = idx >> 3, c = (idx & 7) * 4;
                ra[p] = *(const float4*)&x[(size_t)(r0 + m) * CC + kk + c];
            }
        }

        #pragma unroll
        for (int k2 = 0; k2 < 32; k2 += 16) {
            uint32_t a[2][4], b[4][4];
            #pragma unroll
            for (int ms = 0; ms < 2; ms++) {
                uint32_t ad = (uint32_t)__cvta_generic_to_shared(
                    &As[(size_t)(pb * 128 + wm * 32 + ms * 16 + lrow) * 40 + k2 + lkof]);
                ldsm4(a[ms], ad);
            }
            #pragma unroll
            for (int nb = 0; nb < 4; nb++) {
                uint32_t bd = (uint32_t)__cvta_generic_to_shared(
                    &Bs[(size_t)(pb * 256 + wn * 64 + nb * 16 + lrow) * 40 + k2 + lkof]);
                ldsm4(b[nb], bd);
            }
            #pragma unroll
            for (int ms = 0; ms < 2; ms++)
                #pragma unroll
                for (int ns = 0; ns < 8; ns++) {
                    int nb = ns >> 1, odd = ns & 1;
                    mma_bf16(acc[ms][ns], a[ms], b[nb][odd], b[nb][odd + 2]);
                }
        }

        if (t < 7) {
            const int pn = pb ^ 1;
            const int kk = (t + 1) * 32;
            #pragma unroll
            for (int p = 0; p < 2; p++) {
                int idx = p * GEMM_THREADS + tid;
                int m = idx >> 3, c = (idx & 7) * 4;
                int kg = kk + myc;
                sat[p] += ra[p].x*d_vt[kg] + ra[p].y*d_vt[kg+1] + ra[p].z*d_vt[kg+2] + ra[p].w*d_vt[kg+3];
                sap[p] += ra[p].x*d_vp[kg] + ra[p].y*d_vp[kg+1] + ra[p].z*d_vp[kg+2] + ra[p].w*d_vp[kg+3];
                __nv_bfloat162 lo = __floats2bfloat162_rn(ra[p].x, ra[p].y);
                __nv_bfloat162 hi = __floats2bfloat162_rn(ra[p].z, ra[p].w);
                uint2 pk; pk.x = *(uint32_t*)&lo; pk.y = *(uint32_t*)&hi;
                *(uint2*)&As[(size_t)(pn * 128 + m) * 40 + c] = pk;
            }
            cp_wait0();
        }
        __syncthreads();
    }

    // ---- score reduction across the 8 lanes sharing a row ----
    #pragma unroll
    for (int p = 0; p < 2; p++) {
        #pragma unroll
        for (int o = 1; o < 8; o <<= 1) {
            sat[p] += __shfl_xor_sync(0xffffffffu, sat[p], o);
            sap[p] += __shfl_xor_sync(0xffffffffu, sap[p], o);
        }
    }
    if ((tid & 7) == 0) {
        #pragma unroll
        for (int p = 0; p < 2; p++) {
            int row = r0 + p * 64 + (tid >> 3);
            float st = sat[p] + d_ct;
            d_st[row] = st;
            d_sp[row] = sap[p] + d_cp;
            int j = row & (NN - 1);
            d_skey[row] = (f2sortable(st) & ~0xFFFu) | (unsigned)(NN - 1 - j);
        }
    }

    // ---- epilogue: h = acc + chb -> bf16 ----
    #pragma unroll
    for (int ns = 0; ns < 8; ns++) {
        int col = wn * 64 + ns * 8 + (lane & 3) * 2;
        float b0 = d_chb[col], b1 = d_chb[col + 1];
        #pragma unroll
        for (int ms = 0; ms < 2; ms++) {
            int row = r0 + wm * 32 + ms * 16 + (lane >> 2);
            __nv_bfloat162 v0 = __floats2bfloat162_rn(acc[ms][ns][0] + b0, acc[ms][ns][1] + b1);
            __nv_bfloat162 v1 = __floats2bfloat162_rn(acc[ms][ns][2] + b0, acc[ms][ns][3] + b1);
            *(uint32_t*)&d_hb[(size_t)row * CC + col] = *(uint32_t*)&v0;
            *(uint32_t*)&d_hb[(size_t)(row + 8) * CC + col] = *(uint32_t*)&v1;
        }
    }
}

// ---------------- K3: persistent megakernel: rank -> scanA -> scanB -> out ----
__global__ __launch_bounds__(256) void k_mega(const float* __restrict__ x,
                                              float* __restrict__ out,
                                              int nBlocks) {
    __shared__ unsigned sbuf[NN];       // 16 KB (keys / sorted keys)
    __shared__ int   part[256];
    __shared__ int   sIdx[SEG];
    __shared__ float sT[SEG];
    __shared__ float sps[32];
    __shared__ int   ks[32];
    const int tid = threadIdx.x;

    // ---- phase R: rank + scatter (128 tasks) ----
    for (int task = blockIdx.x; task < NN / 128 * BB; task += nBlocks) {
        int b = task >> 5, xi = task & 31;
        const uint4* g4 = (const uint4*)(d_skey + b * NN);
        uint4* s4w = (uint4*)sbuf;
        #pragma unroll
        for (int q = 0; q < 4; q++) s4w[q * 256 + tid] = g4[q * 256 + tid];
        __syncthreads();
        int r = tid & 127, half = tid >> 7;
        int i = xi * 128 + r;
        unsigned v = sbuf[i];
        const uint4* s4 = (const uint4*)(sbuf + half * (NN / 2));
        int rank = 0;
        #pragma unroll 8
        for (int j4 = 0; j4 < NN / 8; j4++) {
            uint4 m = s4[j4];
            rank += (m.x > v) + (m.y > v) + (m.z > v) + (m.w > v);
        }
        part[tid] = rank;
        __syncthreads();
        if (half == 0) d_ksort[b * NN + rank + part[tid + 128]] = v;
        __syncthreads();
    }
    grid_barrier(nBlocks);

    // ---- phase A: segmented prefix sums (512 tasks) ----
    for (int task = blockIdx.x; task < BB * NSEG; task += nBlocks) {
        int b = task >> 7, s = task & 127;
        int base = b * NN + s * SEG;
        int c = tid;
        if (tid < SEG) {
            unsigned kk = d_ksort[base + tid];
            int j = (NN - 1) - (int)(kk & 0xFFFu);
            sIdx[tid] = j;
            sT[tid] = d_st[b * NN + j];
        }
        __syncthreads();
        float hv[SEG];
        #pragma unroll
        for (int r = 0; r < SEG; r++)
            hv[r] = __bfloat162float(d_hb[(size_t)(b * NN + sIdx[r]) * CC + c]);
        float a1 = 0.f, a2 = 0.f;
        #pragma unroll
        for (int r = 0; r < SEG; r++) {
            a1 += hv[r];
            a2 = fmaf(sT[r], hv[r], a2);
            d_Q[(size_t)(base + r) * CC + c] = __floats2bfloat162_rn(a1, a2);
        }
        d_seg[(b * NSEG + s) * CC + c] = make_float2(a1, a2);
        __syncthreads();
    }
    grid_barrier(nBlocks);

    // ---- phase B: exclusive scan of segment totals (4 tasks) ----
    for (int task = blockIdx.x; task < BB; task += nBlocks) {
        int b = task, c = tid;
        float a1 = 0.f, a2 = 0.f;
        #pragma unroll 4
        for (int s = 0; s < NSEG; s++) {
            int idx = (b * NSEG + s) * CC + c;
            float2 v = d_seg[idx];
            d_off[idx] = make_float2(a1, a2);
            a1 += v.x;
            a2 += v.y;
        }
    }
    grid_barrier(nBlocks);

    // ---- phase O: streaming output (512 tasks) ----
    for (int task = blockIdx.x; task < ROWS / 32; task += nBlocks) {
        int gr0 = task * 32;
        int b = gr0 / NN;
        __syncthreads();   // protect sbuf from previous iteration's readers
        {
            const uint4* g4 = (const uint4*)(d_ksort + b * NN);
            uint4* s4 = (uint4*)sbuf;
            #pragma unroll
            for (int q = 0; q < 4; q++) s4[q * 256 + tid] = g4[q * 256 + tid];
        }
        __syncthreads();
        if (tid < 32) {
            int i = gr0 + tid;
            float sp = d_sp[i];
            sps[tid] = sp;
            unsigned mth = (f2sortable(-sp) & ~0xFFFu) | 0xFFFu;
            int lo = 0, hi = NN;
            while (lo < hi) {
                int mid = (lo + hi) >> 1;
                if (sbuf[mid] > mth) lo = mid + 1; else hi = mid;
            }
            ks[tid] = lo;
        }
        __syncthreads();
        const float invn = 1.f / NN;
        const int c = tid;
        const float sc = d_scale[c], sh = d_shift[c];
        #pragma unroll 8
        for (int rr = 0; rr < 32; rr++) {
            int i = gr0 + rr;
            int k = ks[rr];
            float q1 = 0.f, q2 = 0.f;
            if (k > 0) {
                float2 q = __bfloat1622float2(d_Q[(size_t)(b * NN + k - 1) * CC + c]);
                float2 o = d_off[(b * NSEG + ((k - 1) >> 5)) * CC + c];
                q1 = q.x + o.x;
                q2 = q.y + o.y;
            }
            float y = (sps[rr] * q1 + q2) * invn;
            size_t gi = (size_t)i * CC + c;
            out[gi] = fmaf(y, sc, sh) + x[gi];
        }
    }
}

// ---------------- fallback kernels (legacy 6-node path) -----------------------
__global__ __launch_bounds__(256) void k_rank1() {
    __shared__ unsigned keys[NN];
    __shared__ int part[256];
    const int b = blockIdx.y;
    const int tid = threadIdx.x;
    const uint4* g4 = (const uint4*)(d_skey + b * NN);
    uint4* s4w = (uint4*)keys;
    #pragma unroll
    for (int q = 0; q < 4; q++) s4w[q * 256 + tid] = g4[q * 256 + tid];
    __syncthreads();
    const int r = tid & 127;
    const int half = tid >> 7;
    const int i = blockIdx.x * 128 + r;
    const unsigned v = keys[i];
    const uint4* s4 = (const uint4*)(keys + half * (NN / 2));
    int rank = 0;
    #pragma unroll 8
    for (int j4 = 0; j4 < NN / 8; j4++) {
        uint4 m = s4[j4];
        rank += (m.x > v) + (m.y > v) + (m.z > v) + (m.w > v);
    }
    part[tid] = rank;
    __syncthreads();
    if (half == 0) {
        int rk = rank + part[tid + 128];
        d_ksort[b * NN + rk] = v;
    }
}

__global__ __launch_bounds__(256) void k_scanA() {
    __shared__ int   sIdx[SEG];
    __shared__ float sT[SEG];
    const int b = blockIdx.y, s = blockIdx.x, c = threadIdx.x;
    const int base = b * NN + s * SEG;
    if (c < SEG) {
        unsigned kk = d_ksort[base + c];
        int j = (NN - 1) - (int)(kk & 0xFFFu);
        sIdx[c] = j;
        sT[c] = d_st[b * NN + j];
    }
    __syncthreads();
    float hv[SEG];
    #pragma unroll
    for (int r = 0; r < SEG; r++)
        hv[r] = __bfloat162float(d_hb[(size_t)(b * NN + sIdx[r]) * CC + c]);
    float a1 = 0.f, a2 = 0.f;
    #pragma unroll
    for (int r = 0; r < SEG; r++) {
        a1 += hv[r];
        a2 = fmaf(sT[r], hv[r], a2);
        d_Q[(size_t)(base + r) * CC + c] = __floats2bfloat162_rn(a1, a2);
    }
    d_seg[(b * NSEG + s) * CC + c] = make_float2(a1, a2);
}

__global__ __launch_bounds__(256) void k_scanB() {
    const int b = blockIdx.x, c = threadIdx.x;
    float a1 = 0.f, a2 = 0.f;
    #pragma unroll 4
    for (int s = 0; s < NSEG; s++) {
        int idx = (b * NSEG + s) * CC + c;
        float2 v = d_seg[idx];
        d_off[idx] = make_float2(a1, a2);
        a1 += v.x;
        a2 += v.y;
    }
}

__global__ __launch_bounds__(256) void k_out(const float* __restrict__ x,
                                             float* __restrict__ out) {
    __shared__ unsigned sk[NN];
    __shared__ float sps[32];
    __shared__ int   ks[32];
    const int gr0 = blockIdx.x * 32;
    const int b   = gr0 / NN;
    const int tid = threadIdx.x;
    {
        const uint4* g4 = (const uint4*)(d_ksort + b * NN);
        uint4* s4 = (uint4*)sk;
        #pragma unroll
        for (int q = 0; q < 4; q++) s4[q * 256 + tid] = g4[q * 256 + tid];
    }
    __syncthreads();
    if (tid < 32) {
        int i = gr0 + tid;
        float sp = d_sp[i];
        sps[tid] = sp;
        unsigned mth = (f2sortable(-sp) & ~0xFFFu) | 0xFFFu;
        int lo = 0, hi = NN;
        while (lo < hi) {
            int mid = (lo + hi) >> 1;
            if (sk[mid] > mth) lo = mid + 1; else hi = mid;
        }
        ks[tid] = lo;
    }
    __syncthreads();
    const float invn = 1.f / NN;
    const int c = tid;
    const float sc = d_scale[c], sh = d_shift[c];
    #pragma unroll 8
    for (int rr = 0; rr < 32; rr++) {
        int i = gr0 + rr;
        int k = ks[rr];
        float q1 = 0.f, q2 = 0.f;
        if (k > 0) {
            float2 q = __bfloat1622float2(d_Q[(size_t)(b * NN + k - 1) * CC + c]);
            float2 o = d_off[(b * NSEG + ((k - 1) >> 5)) * CC + c];
            q1 = q.x + o.x;
            q2 = q.y + o.y;
        }
        float y = (sps[rr] * q1 + q2) * invn;
        size_t gi = (size_t)i * CC + c;
        out[gi] = fmaf(y, sc, sh) + x[gi];
    }
}

// ---------------- launch -----------------------------------------------------
extern "C" void kernel_launch(void* const* d_in, const int* in_sizes, int n_in,
                              void* d_out, int out_size) {
    const float* x      = (const float*)d_in[0];
    const float* wg     = (const float*)d_in[1];
    const float* bg     = (const float*)d_in[2];
    const float* wt     = (const float*)d_in[3];
    const float* bt     = (const float*)d_in[4];
    const float* wp     = (const float*)d_in[5];
    const float* bp     = (const float*)d_in[6];
    const float* wc     = (const float*)d_in[7];
    const float* ww     = (const float*)d_in[8];
    const float* bw     = (const float*)d_in[9];
    const float* gamma  = (const float*)d_in[10];
    const float* beta   = (const float*)d_in[11];
    const float* bnmean = (const float*)d_in[12];
    const float* bnvar  = (const float*)d_in[13];
    float* out = (float*)d_out;

    static int megaGrid = -2;   // -2 = uninitialized, -1 = fallback
    if (megaGrid == -2) {
        cudaFuncSetAttribute((const void*)k_gemm,
                             cudaFuncAttributeMaxDynamicSharedMemorySize, GEMM_SMEM);
        int sms = 0, occ = 0;
        cudaDeviceGetAttribute(&sms, cudaDevAttrMultiProcessorCount, 0);
        cudaOccupancyMaxActiveBlocksPerMultiprocessor(&occ, k_mega, 256, 0);
        if (sms > 0 && occ >= 1) {
            int g = sms * (occ >= 2 ? 2 : 1);
            if (g > 512) g = 512;          // never more blocks than max tasks
            megaGrid = g;
        } else {
            megaGrid = -1;
        }
    }

    k_prep<<<CC, 128>>>(wg, ww, bg, wt, wp, wc, bt, bp, gamma, beta, bnmean, bnvar, bw);
    k_gemm<<<ROWS / 128, GEMM_THREADS, GEMM_SMEM>>>(x);

    if (megaGrid > 0) {
        k_mega<<<megaGrid, 256>>>(x, out, megaGrid);
    } else {
        k_rank1<<<dim3(NN / 128, BB), 256>>>();
        k_scanA<<<dim3(NSEG, BB), 256>>>();
        k_scanB<<<BB, 256>>>();
        k_out<<<ROWS / 32, 256>>>(x, out);
    }
}

// round 16
// speedup vs baseline: 1.6913x; 1.6913x over previous
#include <cuda_runtime.h>
#include <cuda_bf16.h>
#include <cstdint>

#define BB 4
#define NN 4096
#define CC 256
#define II 128
#define ROWS (BB*NN)          // 16384
#define SEG 32
#define NSEG (NN/SEG)         // 128
#define BN_EPS 1e-3f

#define GEMM_THREADS 512
#define GEMM_SMEM (2*128*40*2 + 2*256*40*2)   // 61440 bytes

// ---------------- scratch (static device allocations) ----------------
__device__ float d_vt[CC], d_vp[CC];
__device__ float d_ct, d_cp;
__device__ float d_scale[CC], d_shift[CC];
__device__ __nv_bfloat16 d_Wt[CC*CC];       // Wt[n][k] = (wg@ww)[k][n], bf16
__device__ float d_chb[CC];                 // bg @ ww
__device__ __nv_bfloat16 d_hb[(size_t)ROWS*CC];   // h = x@W + chb, bf16 (8 MB)
__device__ float d_st[ROWS], d_sp[ROWS];
__device__ unsigned d_skey[ROWS];           // truncated sortable key | (4095-j)
__device__ unsigned d_ksort[ROWS];          // keys in descending order
__device__ __nv_bfloat162 d_Q[(size_t)ROWS*CC];   // (prefix h, prefix t*h) bf16 (8 MB)
__device__ float2 d_seg[BB*NSEG*CC];        // segment totals
__device__ float2 d_off[BB*NSEG*CC];        // exclusive segment offsets

// ---------------- helpers ----------------------------------------------------
__device__ __forceinline__ unsigned f2sortable(float f) {
    unsigned u = __float_as_uint(f);
    return (u & 0x80000000u) ? ~u : (u | 0x80000000u);
}
__device__ __forceinline__ void ldsm4(uint32_t* r, uint32_t addr) {
    asm volatile("ldmatrix.sync.aligned.m8n8.x4.shared.b16 {%0,%1,%2,%3},[%4];\n"
        : "=r"(r[0]), "=r"(r[1]), "=r"(r[2]), "=r"(r[3]) : "r"(addr));
}
__device__ __forceinline__ void mma_bf16(float* c, const uint32_t* a, uint32_t b0, uint32_t b1) {
    asm volatile("mma.sync.aligned.m16n8k16.row.col.f32.bf16.bf16.f32 "
        "{%0,%1,%2,%3},{%4,%5,%6,%7},{%8,%9},{%0,%1,%2,%3};\n"
        : "+f"(c[0]), "+f"(c[1]), "+f"(c[2]), "+f"(c[3])
        : "r"(a[0]), "r"(a[1]), "r"(a[2]), "r"(a[3]), "r"(b0), "r"(b1));
}
__device__ __forceinline__ void cp_async16(uint32_t saddr, const void* gaddr) {
    asm volatile("cp.async.cg.shared.global [%0], [%1], 16;\n" :: "r"(saddr), "l"(gaddr));
}
__device__ __forceinline__ void cp_commit() {
    asm volatile("cp.async.commit_group;\n");
}
__device__ __forceinline__ void cp_wait0() {
    asm volatile("cp.async.wait_group 0;\n");
}

// ---------------- K0: W = wg@ww, coalesced over n (block = row c) -------------
// block c (0..255), 256 threads = n. ww reads fully coalesced.
__global__ __launch_bounds__(256) void k_prep(const float* __restrict__ wg,
                                              const float* __restrict__ ww,
                                              const float* __restrict__ bg,
                                              const float* __restrict__ wt,
                                              const float* __restrict__ wp,
                                              const float* __restrict__ wc,
                                              const float* __restrict__ bt,
                                              const float* __restrict__ bp,
                                              const float* __restrict__ gamma,
                                              const float* __restrict__ beta,
                                              const float* __restrict__ bn_mean,
                                              const float* __restrict__ bn_var,
                                              const float* __restrict__ bw) {
    __shared__ float wgrow[II];
    const int c = blockIdx.x;          // 0..255  (W row)
    const int t = threadIdx.x;         // 0..255  (W col)
    if (t < II) wgrow[t] = wg[c * II + t];
    __syncthreads();
    float s = 0.f;
    #pragma unroll 8
    for (int j = 0; j < II; j++) s = fmaf(wgrow[j], ww[j * CC + t], s);
    d_Wt[t * CC + c] = __float2bfloat16(s);

    if (c == 0) {
        // chb[n] = sum_j bg[j]*ww[j][n]  (coalesced over n)
        float sb = 0.f;
        #pragma unroll 8
        for (int j = 0; j < II; j++) sb = fmaf(bg[j], ww[j * CC + t], sb);
        d_chb[t] = sb;
        float a = gamma[t] * rsqrtf(bn_var[t] + BN_EPS);
        d_scale[t] = a;
        d_shift[t] = (bw[t] - bn_mean[t]) * a + beta[t];
    } else if (c == 1) {
        // vt[n] = sum_k wt[n][k]*wc[k] : warp per 32 outputs, lane-strided k
        int warp = t >> 5, lane = t & 31;
        #pragma unroll
        for (int i = 0; i < 32; i++) {
            int n = warp * 32 + i;
            float a = 0.f;
            #pragma unroll
            for (int k = lane; k < II; k += 32) a = fmaf(wt[n * II + k], wc[k], a);
            #pragma unroll
            for (int o = 16; o; o >>= 1) a += __shfl_xor_sync(0xffffffffu, a, o);
            if (lane == 0) d_vt[n] = a;
        }
    } else if (c == 2) {
        int warp = t >> 5, lane = t & 31;
        #pragma unroll
        for (int i = 0; i < 32; i++) {
            int n = warp * 32 + i;
            float a = 0.f;
            #pragma unroll
            for (int k = lane; k < II; k += 32) a = fmaf(wp[n * II + k], wc[II + k], a);
            #pragma unroll
            for (int o = 16; o; o >>= 1) a += __shfl_xor_sync(0xffffffffu, a, o);
            if (lane == 0) d_vp[n] = a;
        }
    } else if (c == 3) {
        // scalars ct, cp via warp reductions (warps 0 and 1)
        int warp = t >> 5, lane = t & 31;
        if (warp == 0) {
            float a = 0.f;
            #pragma unroll
            for (int k = lane; k < II; k += 32) a = fmaf(bt[k], wc[k], a);
            #pragma unroll
            for (int o = 16; o; o >>= 1) a += __shfl_xor_sync(0xffffffffu, a, o);
            if (lane == 0) d_ct = a;
        } else if (warp == 1) {
            float a = 0.f;
            #pragma unroll
            for (int k = lane; k < II; k += 32) a = fmaf(bp[k], wc[II + k], a);
            #pragma unroll
            for (int o = 16; o; o >>= 1) a += __shfl_xor_sync(0xffffffffu, a, o);
            if (lane == 0) d_cp = a;
        }
    }
}

// ---------------- K2: h = x@W + chb, BM=128 x BN=256, one wave ---------------
// 512 threads, 16 warps (4m x 4n), double-buffered; B tiles via cp.async.
__global__ __launch_bounds__(GEMM_THREADS, 1) void k_gemm(const float* __restrict__ x) {
    extern __shared__ __nv_bfloat16 smemb[];
    __nv_bfloat16* As = smemb;                    // [2][128][40]
    __nv_bfloat16* Bs = smemb + 2 * 128 * 40;     // [2][256][40]
    const int tid  = threadIdx.x;
    const int warp = tid >> 5, lane = tid & 31;
    const int wm = warp & 3, wn = warp >> 2;
    const int r0 = blockIdx.x * 128;

    float acc[2][8][4];
    #pragma unroll
    for (int ms = 0; ms < 2; ms++)
        #pragma unroll
        for (int ns = 0; ns < 8; ns++)
            #pragma unroll
            for (int q = 0; q < 4; q++) acc[ms][ns][q] = 0.f;

    float sat[2] = {0.f, 0.f}, sap[2] = {0.f, 0.f};
    const int myc = (tid & 7) * 4;

    const int lrow = lane & 15;
    const int lkof = (lane >> 4) << 3;

    const int bn0 = (tid) >> 2,                bk0 = (tid & 3) * 8;
    const int bn1 = (GEMM_THREADS + tid) >> 2, bk1 = ((GEMM_THREADS + tid) & 3) * 8;

    // ---- prologue: tile 0 ----
    cp_async16((uint32_t)__cvta_generic_to_shared(&Bs[(size_t)bn0 * 40 + bk0]),
               &d_Wt[bn0 * CC + bk0]);
    cp_async16((uint32_t)__cvta_generic_to_shared(&Bs[(size_t)bn1 * 40 + bk1]),
               &d_Wt[bn1 * CC + bk1]);
    cp_commit();
    #pragma unroll
    for (int p = 0; p < 2; p++) {
        int idx = p * GEMM_THREADS + tid;
        int m = idx >> 3, c = (idx & 7) * 4;
        float4 v = *(const float4*)&x[(size_t)(r0 + m) * CC + c];
        sat[p] += v.x*d_vt[myc] + v.y*d_vt[myc+1] + v.z*d_vt[myc+2] + v.w*d_vt[myc+3];
        sap[p] += v.x*d_vp[myc] + v.y*d_vp[myc+1] + v.z*d_vp[myc+2] + v.w*d_vp[myc+3];
        __nv_bfloat162 lo = __floats2bfloat162_rn(v.x, v.y);
        __nv_bfloat162 hi = __floats2bfloat162_rn(v.z, v.w);
        uint2 pk; pk.x = *(uint32_t*)&lo; pk.y = *(uint32_t*)&hi;
        *(uint2*)&As[(size_t)m * 40 + c] = pk;
    }
    cp_wait0();
    __syncthreads();

    #pragma unroll
    for (int t = 0; t < 8; t++) {
        const int pb = t & 1;
        float4 ra[2];
        if (t < 7) {
            const int kk = (t + 1) * 32;
            const int pn = pb ^ 1;
            cp_async16((uint32_t)__cvta_generic_to_shared(
                           &Bs[(size_t)(pn * 256 + bn0) * 40 + bk0]),
                       &d_Wt[bn0 * CC + kk + bk0]);
            cp_async16((uint32_t)__cvta_generic_to_shared(
                           &Bs[(size_t)(pn * 256 + bn1) * 40 + bk1]),
                       &d_Wt[bn1 * CC + kk + bk1]);
            cp_commit();
            #pragma unroll
            for (int p = 0; p < 2; p++) {
                int idx = p * GEMM_THREADS + tid;
                int m = idx >> 3, c = (idx & 7) * 4;
                ra[p] = *(const float4*)&x[(size_t)(r0 + m) * CC + kk + c];
            }
        }

        #pragma unroll
        for (int k2 = 0; k2 < 32; k2 += 16) {
            uint32_t a[2][4], b[4][4];
            #pragma unroll
            for (int ms = 0; ms < 2; ms++) {
                uint32_t ad = (uint32_t)__cvta_generic_to_shared(
                    &As[(size_t)(pb * 128 + wm * 32 + ms * 16 + lrow) * 40 + k2 + lkof]);
                ldsm4(a[ms], ad);
            }
            #pragma unroll
            for (int nb = 0; nb < 4; nb++) {
                uint32_t bd = (uint32_t)__cvta_generic_to_shared(
                    &Bs[(size_t)(pb * 256 + wn * 64 + nb * 16 + lrow) * 40 + k2 + lkof]);
                ldsm4(b[nb], bd);
            }
            #pragma unroll
            for (int ms = 0; ms < 2; ms++)
                #pragma unroll
                for (int ns = 0; ns < 8; ns++) {
                    int nb = ns >> 1, odd = ns & 1;
                    mma_bf16(acc[ms][ns], a[ms], b[nb][odd], b[nb][odd + 2]);
                }
        }

        if (t < 7) {
            const int pn = pb ^ 1;
            const int kk = (t + 1) * 32;
            #pragma unroll
            for (int p = 0; p < 2; p++) {
                int idx = p * GEMM_THREADS + tid;
                int m = idx >> 3, c = (idx & 7) * 4;
                int kg = kk + myc;
                sat[p] += ra[p].x*d_vt[kg] + ra[p].y*d_vt[kg+1] + ra[p].z*d_vt[kg+2] + ra[p].w*d_vt[kg+3];
                sap[p] += ra[p].x*d_vp[kg] + ra[p].y*d_vp[kg+1] + ra[p].z*d_vp[kg+2] + ra[p].w*d_vp[kg+3];
                __nv_bfloat162 lo = __floats2bfloat162_rn(ra[p].x, ra[p].y);
                __nv_bfloat162 hi = __floats2bfloat162_rn(ra[p].z, ra[p].w);
                uint2 pk; pk.x = *(uint32_t*)&lo; pk.y = *(uint32_t*)&hi;
                *(uint2*)&As[(size_t)(pn * 128 + m) * 40 + c] = pk;
            }
            cp_wait0();
        }
        __syncthreads();
    }

    // ---- score reduction across the 8 lanes sharing a row ----
    #pragma unroll
    for (int p = 0; p < 2; p++) {
        #pragma unroll
        for (int o = 1; o < 8; o <<= 1) {
            sat[p] += __shfl_xor_sync(0xffffffffu, sat[p], o);
            sap[p] += __shfl_xor_sync(0xffffffffu, sap[p], o);
        }
    }
    if ((tid & 7) == 0) {
        #pragma unroll
        for (int p = 0; p < 2; p++) {
            int row = r0 + p * 64 + (tid >> 3);
            float st = sat[p] + d_ct;
            d_st[row] = st;
            d_sp[row] = sap[p] + d_cp;
            int j = row & (NN - 1);
            d_skey[row] = (f2sortable(st) & ~0xFFFu) | (unsigned)(NN - 1 - j);
        }
    }

    // ---- epilogue: h = acc + chb -> bf16 ----
    #pragma unroll
    for (int ns = 0; ns < 8; ns++) {
        int col = wn * 64 + ns * 8 + (lane & 3) * 2;
        float b0 = d_chb[col], b1 = d_chb[col + 1];
        #pragma unroll
        for (int ms = 0; ms < 2; ms++) {
            int row = r0 + wm * 32 + ms * 16 + (lane >> 2);
            __nv_bfloat162 v0 = __floats2bfloat162_rn(acc[ms][ns][0] + b0, acc[ms][ns][1] + b1);
            __nv_bfloat162 v1 = __floats2bfloat162_rn(acc[ms][ns][2] + b0, acc[ms][ns][3] + b1);
            *(uint32_t*)&d_hb[(size_t)row * CC + col] = *(uint32_t*)&v0;
            *(uint32_t*)&d_hb[(size_t)(row + 8) * CC + col] = *(uint32_t*)&v1;
        }
    }
}

// ---------------- K3: full rank + scatter (256 thr, 2/row) --------------------
__global__ __launch_bounds__(256) void k_rank1() {
    __shared__ unsigned keys[NN];      // 16 KB
    __shared__ int part[256];
    const int b = blockIdx.y;
    const int tid = threadIdx.x;
    const uint4* g4 = (const uint4*)(d_skey + b * NN);
    uint4* s4w = (uint4*)keys;
    #pragma unroll
    for (int q = 0; q < 4; q++) s4w[q * 256 + tid] = g4[q * 256 + tid];
    __syncthreads();
    const int r = tid & 127;
    const int half = tid >> 7;
    const int i = blockIdx.x * 128 + r;
    const unsigned v = keys[i];
    const uint4* s4 = (const uint4*)(keys + half * (NN / 2));
    int rank = 0;
    #pragma unroll 8
    for (int j4 = 0; j4 < NN / 8; j4++) {
        uint4 m = s4[j4];
        rank += (m.x > v) + (m.y > v) + (m.z > v) + (m.w > v);
    }
    part[tid] = rank;
    __syncthreads();
    if (half == 0) {
        int rk = rank + part[tid + 128];
        d_ksort[b * NN + rk] = v;
    }
}

// ---------------- K4: segmented prefix sums (exact t/j recovered from key) ----
__global__ __launch_bounds__(256) void k_scanA() {
    __shared__ int   sIdx[SEG];
    __shared__ float sT[SEG];
    const int b = blockIdx.y, s = blockIdx.x, c = threadIdx.x;
    const int base = b * NN + s * SEG;
    if (c < SEG) {
        unsigned kk = d_ksort[base + c];
        int j = (NN - 1) - (int)(kk & 0xFFFu);
        sIdx[c] = j;
        sT[c] = d_st[b * NN + j];
    }
    __syncthreads();
    float hv[SEG];
    #pragma unroll
    for (int r = 0; r < SEG; r++)
        hv[r] = __bfloat162float(d_hb[(size_t)(b * NN + sIdx[r]) * CC + c]);
    float a1 = 0.f, a2 = 0.f;
    #pragma unroll
    for (int r = 0; r < SEG; r++) {
        a1 += hv[r];
        a2 = fmaf(sT[r], hv[r], a2);
        d_Q[(size_t)(base + r) * CC + c] = __floats2bfloat162_rn(a1, a2);
    }
    d_seg[(b * NSEG + s) * CC + c] = make_float2(a1, a2);
}

// ---------------- K5: exclusive scan of segment totals ------------------------
__global__ __launch_bounds__(256) void k_scanB() {
    const int b = blockIdx.x, c = threadIdx.x;
    float a1 = 0.f, a2 = 0.f;
    #pragma unroll 4
    for (int s = 0; s < NSEG; s++) {
        int idx = (b * NSEG + s) * CC + c;
        float2 v = d_seg[idx];
        d_off[idx] = make_float2(a1, a2);
        a1 += v.x;
        a2 += v.y;
    }
}

// ---------------- K6: streaming output (32 rows/block) ------------------------
__global__ __launch_bounds__(256) void k_out(const float* __restrict__ x,
                                             float* __restrict__ out) {
    __shared__ unsigned sk[NN];        // 16 KB: this batch's sorted keys
    __shared__ float sps[32];
    __shared__ int   ks[32];
    const int gr0 = blockIdx.x * 32;
    const int b   = gr0 / NN;
    const int tid = threadIdx.x;
    {
        const uint4* g4 = (const uint4*)(d_ksort + b * NN);
        uint4* s4 = (uint4*)sk;
        #pragma unroll
        for (int q = 0; q < 4; q++) s4[q * 256 + tid] = g4[q * 256 + tid];
    }
    __syncthreads();
    if (tid < 32) {
        int i = gr0 + tid;
        float sp = d_sp[i];
        sps[tid] = sp;
        unsigned mth = (f2sortable(-sp) & ~0xFFFu) | 0xFFFu;
        int lo = 0, hi = NN;
        while (lo < hi) {
            int mid = (lo + hi) >> 1;
            if (sk[mid] > mth) lo = mid + 1; else hi = mid;
        }
        ks[tid] = lo;
    }
    __syncthreads();
    const float invn = 1.f / NN;
    const int c = tid;
    const float sc = d_scale[c], sh = d_shift[c];
    #pragma unroll 8
    for (int rr = 0; rr < 32; rr++) {
        int i = gr0 + rr;
        int k = ks[rr];
        float q1 = 0.f, q2 = 0.f;
        if (k > 0) {
            float2 q = __bfloat1622float2(d_Q[(size_t)(b * NN + k - 1) * CC + c]);
            float2 o = d_off[(b * NSEG + ((k - 1) >> 5)) * CC + c];
            q1 = q.x + o.x;
            q2 = q.y + o.y;
        }
        float y = (sps[rr] * q1 + q2) * invn;
        size_t gi = (size_t)i * CC + c;
        out[gi] = fmaf(y, sc, sh) + x[gi];
    }
}

// ---------------- launch -----------------------------------------------------
extern "C" void kernel_launch(void* const* d_in, const int* in_sizes, int n_in,
                              void* d_out, int out_size) {
    const float* x      = (const float*)d_in[0];
    const float* wg     = (const float*)d_in[1];
    const float* bg     = (const float*)d_in[2];
    const float* wt     = (const float*)d_in[3];
    const float* bt     = (const float*)d_in[4];
    const float* wp     = (const float*)d_in[5];
    const float* bp     = (const float*)d_in[6];
    const float* wc     = (const float*)d_in[7];
    const float* ww     = (const float*)d_in[8];
    const float* bw     = (const float*)d_in[9];
    const float* gamma  = (const float*)d_in[10];
    const float* beta   = (const float*)d_in[11];
    const float* bnmean = (const float*)d_in[12];
    const float* bnvar  = (const float*)d_in[13];
    float* out = (float*)d_out;

    static bool attrDone = false;
    if (!attrDone) {
        cudaFuncSetAttribute((const void*)k_gemm,
                             cudaFuncAttributeMaxDynamicSharedMemorySize, GEMM_SMEM);
        attrDone = true;
    }

    k_prep<<<CC, 256>>>(wg, ww, bg, wt, wp, wc, bt, bp, gamma, beta, bnmean, bnvar, bw);
    k_gemm<<<ROWS / 128, GEMM_THREADS, GEMM_SMEM>>>(x);
    k_rank1<<<dim3(NN / 128, BB), 256>>>();
    k_scanA<<<dim3(NSEG, BB), 256>>>();
    k_scanB<<<BB, 256>>>();
    k_out<<<ROWS / 32, 256>>>(x, out);
}